// round 5
// baseline (speedup 1.0000x reference)
#include <cuda_runtime.h>
#include <cstdint>
#include <cstddef>

#define BB 64
#define TT 512
#define II 128
#define HH 512
#define NCLS 5

typedef unsigned long long u64;

// Scratch — static __device__ arrays per allocation rules.
__device__ float g_xp[(size_t)BB * TT * HH];
__device__ float g_ys[(size_t)BB * TT * HH];

// ---------------- packed f32x2 helpers ----------------
__device__ __forceinline__ u64 pk2(float x, float y) {
    u64 r; asm("mov.b64 %0, {%1,%2};" : "=l"(r) : "f"(x), "f"(y)); return r;
}
__device__ __forceinline__ float2 upk2(u64 v) {
    float2 f; asm("mov.b64 {%0,%1}, %2;" : "=f"(f.x), "=f"(f.y) : "l"(v)); return f;
}
__device__ __forceinline__ void fma2(u64 &d, u64 a, u64 b) {
    asm("fma.rn.f32x2 %0, %1, %2, %0;" : "+l"(d) : "l"(a), "l"(b));
}

// ---------------- cluster / mbarrier helpers ----------------
__device__ __forceinline__ uint32_t smem_u32(const void* p) {
    uint32_t a;
    asm("{ .reg .u64 t; cvta.to.shared.u64 t, %1; cvt.u32.u64 %0, t; }"
        : "=r"(a) : "l"(p));
    return a;
}
__device__ __forceinline__ uint32_t mapa_u32(uint32_t local, uint32_t rank) {
    uint32_t r;
    asm("mapa.shared::cluster.u32 %0, %1, %2;" : "=r"(r) : "r"(local), "r"(rank));
    return r;
}
__device__ __forceinline__ void st_dsmem4(uint32_t addr, float4 v) {
    asm volatile("st.shared::cluster.v4.f32 [%0], {%1,%2,%3,%4};"
                 :: "r"(addr), "f"(v.x), "f"(v.y), "f"(v.z), "f"(v.w) : "memory");
}
__device__ __forceinline__ void mbar_init(uint32_t addr, uint32_t count) {
    asm volatile("mbarrier.init.shared.b64 [%0], %1;" :: "r"(addr), "r"(count) : "memory");
}
__device__ __forceinline__ void mbar_arrive_remote(uint32_t remote_addr) {
    asm volatile("mbarrier.arrive.release.cluster.shared::cluster.b64 _, [%0];"
                 :: "r"(remote_addr) : "memory");
}
__device__ __forceinline__ void mbar_wait_cluster(uint32_t addr, uint32_t parity) {
    asm volatile(
        "{\n\t"
        ".reg .pred P;\n\t"
        "WLP%=:\n\t"
        "mbarrier.try_wait.parity.acquire.cluster.shared::cta.b64 P, [%0], %1, 0x989680;\n\t"
        "@P bra WDN%=;\n\t"
        "bra WLP%=;\n\t"
        "WDN%=:\n\t"
        "}"
        :: "r"(addr), "r"(parity) : "memory");
}
__device__ __forceinline__ void cluster_sync_full() {
    asm volatile("barrier.cluster.arrive.aligned;" ::: "memory");
    asm volatile("barrier.cluster.wait.aligned;" ::: "memory");
}

// =======================================================================
// GEMM: C[M][HH] = A[M][K] @ W[HH][K]^T + b1 + b2
// Software-pipelined: next tile's LDGs issued right after STS-sync so the
// global-load latency overlaps the tile compute (1 CTA/SM).
// =======================================================================
__global__ void __launch_bounds__(256, 1)
gemm_xproj(const float* __restrict__ A, const float* __restrict__ W,
           const float* __restrict__ b1, const float* __restrict__ b2,
           float* __restrict__ C, int K)
{
    __shared__ u64 As2[8][128];
    __shared__ u64 Bs2[8][128];

    const int tid = threadIdx.x;
    const int m0 = blockIdx.y * 128;
    const int n0 = blockIdx.x * 128;
    const int tx = tid & 15;
    const int ty = tid >> 4;

    const int r0  = tid >> 2;
    const int kq0 = tid & 3;

    u64 acc[8][8];
    #pragma unroll
    for (int i = 0; i < 8; i++)
        #pragma unroll
        for (int j = 0; j < 8; j++) acc[i][j] = 0ull;

    const float* pa0 = &A[(size_t)(m0 + r0)      * K + kq0 * 4];
    const float* pa1 = &A[(size_t)(m0 + 64 + r0) * K + kq0 * 4];
    const float* pw0 = &W[(size_t)(n0 + r0)      * K + kq0 * 4];
    const float* pw1 = &W[(size_t)(n0 + 64 + r0) * K + kq0 * 4];

    const int ktiles = K >> 4;
    float4 a0 = *(const float4*)pa0;
    float4 a1 = *(const float4*)pa1;
    float4 w0 = *(const float4*)pw0;
    float4 w1 = *(const float4*)pw1;

    for (int kt = 0; kt < ktiles; kt++) {
        __syncthreads();
        As2[kq0 * 2][r0]          = pk2(a0.x, a0.y);
        As2[kq0 * 2 + 1][r0]      = pk2(a0.z, a0.w);
        As2[kq0 * 2][64 + r0]     = pk2(a1.x, a1.y);
        As2[kq0 * 2 + 1][64 + r0] = pk2(a1.z, a1.w);
        Bs2[kq0 * 2][r0]          = pk2(w0.x, w0.y);
        Bs2[kq0 * 2 + 1][r0]      = pk2(w0.z, w0.w);
        Bs2[kq0 * 2][64 + r0]     = pk2(w1.x, w1.y);
        Bs2[kq0 * 2 + 1][64 + r0] = pk2(w1.z, w1.w);
        __syncthreads();

        if (kt + 1 < ktiles) {
            const int kb = (kt + 1) * 16;
            a0 = *(const float4*)(pa0 + kb);
            a1 = *(const float4*)(pa1 + kb);
            w0 = *(const float4*)(pw0 + kb);
            w1 = *(const float4*)(pw1 + kb);
        }

        #pragma unroll
        for (int k2 = 0; k2 < 8; k2++) {
            u64 af[8], bf[8];
            #pragma unroll
            for (int i = 0; i < 8; i++) af[i] = As2[k2][ty + 16 * i];
            #pragma unroll
            for (int j = 0; j < 8; j++) bf[j] = Bs2[k2][tx + 16 * j];
            #pragma unroll
            for (int i = 0; i < 8; i++)
                #pragma unroll
                for (int j = 0; j < 8; j++)
                    fma2(acc[i][j], af[i], bf[j]);
        }
    }

    float bias8[8];
    #pragma unroll
    for (int j = 0; j < 8; j++) {
        int n = n0 + tx + 16 * j;
        bias8[j] = b1[n] + b2[n];
    }
    #pragma unroll
    for (int i = 0; i < 8; i++) {
        const size_t m = (size_t)(m0 + ty + 16 * i);
        #pragma unroll
        for (int j = 0; j < 8; j++) {
            float2 p = upk2(acc[i][j]);
            C[m * HH + n0 + tx + 16 * j] = p.x + p.y + bias8[j];
        }
    }
}

// =======================================================================
// Recurrence, direct remote-store exchange.
// 16 clusters x 8 CTAs; CTA r owns output cols [64r,64r+64) of 4 batches.
// h_s[buf][chunk][batch][64]: chunk c = producer c's slice. Per step:
//  - warp kc waits only on chunk kc's mbar (count=8 arrivals)
//  - compute (W in regs), write scalar partials to redv[buf], syncthreads
//  - each thread reduces 8 partials -> final scalar (its (batch,col))
//  - 4-lane shfl assembles float4; 8 lanes/warp st.shared::cluster.v4 the
//    warp's 128B directly into all 8 peers' next h buffer
//  - lane0/warp: 8 remote release-arrives (after syncwarp)
// No staging buffer, no fence, no bulk engine, one syncthreads per step.
// =======================================================================
__global__ void __launch_bounds__(256, 1) __cluster_dims__(8, 1, 1)
rnn_recur(const float* __restrict__ xp, const float* __restrict__ Whh,
          float* __restrict__ ys)
{
    __shared__ ulonglong2 h_s[2][8][4][16];   // [buf][chunk][batch][64 floats] 16KB
    __shared__ float redv[2][8][4][64];       // [buf][chunk][batch][col] 16KB
    __shared__ __align__(8) u64 mbar[2][8];   // [buf][chunk]

    const int tid   = threadIdx.x;
    const int r     = blockIdx.x & 7;         // cluster rank
    const int cl    = blockIdx.x >> 3;
    const int bg    = cl * 4;
    const int jbase = r * 64;

    const int jp = tid & 31;                  // lane
    const int kc = tid >> 5;                  // warp id == consumed chunk
    const int k0 = kc * 64;

    // ---- W_hh slice in registers, k-pair packed ----
    u64 w[2][32];
    #pragma unroll
    for (int jj = 0; jj < 2; jj++) {
        const float* wrow = &Whh[(size_t)(jbase + jp + jj * 32) * HH + k0];
        #pragma unroll
        for (int kp = 0; kp < 32; kp++) {
            float2 wv = *(const float2*)&wrow[2 * kp];
            w[jj][kp] = pk2(wv.x, wv.y);
        }
    }

    // ---- init: zero h buffers, init per-chunk mbarriers (count = 8) ----
    {
        float4* hs = (float4*)h_s;
        for (int i = tid; i < 2 * 8 * 4 * 16; i += 256)
            hs[i] = make_float4(0.f, 0.f, 0.f, 0.f);
    }
    const uint32_t mb_base = smem_u32(&mbar[0][0]);
    const uint32_t hbase   = smem_u32(&h_s[0][0][0][0]);
    if (tid < 16)
        mbar_init(mb_base + (uint32_t)tid * 8u, 8);
    __syncthreads();
    cluster_sync_full();   // peers' mbarriers + buffers ready

    // my-warp wait mbarriers (chunk = kc), buf 0/1
    const uint32_t my_mb[2] = { mb_base + (uint32_t)kc * 8u,
                                mb_base + (uint32_t)(8 + kc) * 8u };
    int par0 = 0, par1 = 0;

    // ---- reduce-role mapping: thread -> (batch, col) ----
    const int cb = tid >> 6;                  // batch (const per warp)
    const int cj = tid & 63;                  // col within this CTA's slice
    const float* xp_ptr = &xp[((size_t)(bg + cb) * TT) * HH + jbase + cj];
    float*       ys_ptr = &ys[((size_t)(bg + cb) * TT) * HH + jbase + cj];

    // ---- remote store targets: chunk r, batch cb, col group cj&~3, all peers ----
    const uint32_t loc_off = (uint32_t)r * 1024u + (uint32_t)cb * 256u
                           + (uint32_t)(cj & ~3) * 4u;
    uint32_t sdst[8];
    #pragma unroll
    for (int q = 0; q < 8; q++)
        sdst[q] = mapa_u32(hbase, (uint32_t)q) + loc_off;

    // ---- remote arrive targets (lane0 of each warp): chunk r mbar, both bufs ----
    uint32_t amb0[8], amb1[8];
    #pragma unroll
    for (int q = 0; q < 8; q++) {
        amb0[q] = mapa_u32(mb_base + (uint32_t)r * 8u,       (uint32_t)q);
        amb1[q] = mapa_u32(mb_base + (uint32_t)(8 + r) * 8u, (uint32_t)q);
    }

    const bool issuer = ((jp & 3) == 0);
    const unsigned lane_base = (unsigned)(jp & ~3);

    for (int t = 0; t < TT; t++) {
        const int os = t & 1;

        const float xpv = __ldg(xp_ptr);

        // ---- per-warp wait for MY chunk only (skip t=0: zeros) ----
        if (t > 0) {
            if (os == 0) { mbar_wait_cluster(my_mb[0], par0); par0 ^= 1; }
            else         { mbar_wait_cluster(my_mb[1], par1); par1 ^= 1; }
        }

        // ---- partial GEMV: W from regs, h broadcast from smem chunk kc ----
        const ulonglong2* hb = &h_s[os][kc][0][0];
        u64 acc0[4], acc1[4];
        #pragma unroll
        for (int b = 0; b < 4; b++) {
            u64 a0 = 0ull, a1 = 0ull;
            #pragma unroll
            for (int kv = 0; kv < 16; kv++) {
                ulonglong2 hv = hb[b * 16 + kv];
                fma2(a0, w[0][2 * kv],     hv.x);
                fma2(a0, w[0][2 * kv + 1], hv.y);
                fma2(a1, w[1][2 * kv],     hv.x);
                fma2(a1, w[1][2 * kv + 1], hv.y);
            }
            acc0[b] = a0; acc1[b] = a1;
        }

        // ---- scalar partials into redv[os] (conflict-free, lane-contiguous) ----
        #pragma unroll
        for (int b = 0; b < 4; b++) {
            float2 p0 = upk2(acc0[b]);
            float2 p1 = upk2(acc1[b]);
            redv[os][kc][b][jp]      = p0.x + p0.y;
            redv[os][kc][b][jp + 32] = p1.x + p1.y;
        }
        __syncthreads();

        // ---- reduce 8 chunks + xproj + relu -> final scalar ----
        float s = xpv;
        #pragma unroll
        for (int c = 0; c < 8; c++) s += redv[os][c][cb][cj];
        s = fmaxf(s, 0.f);

        *ys_ptr = s;                 // coalesced 128B per warp, off critical path
        ys_ptr += HH;
        xp_ptr += HH;

        // ---- exchange: assemble float4, push to all peers, release-arrive ----
        if (t + 1 < TT) {
            float4 v;
            v.x = __shfl_sync(0xffffffffu, s, lane_base);
            v.y = __shfl_sync(0xffffffffu, s, lane_base + 1);
            v.z = __shfl_sync(0xffffffffu, s, lane_base + 2);
            v.w = __shfl_sync(0xffffffffu, s, lane_base + 3);
            const uint32_t boff = ((t + 1) & 1) ? 8192u : 0u;
            if (issuer) {
                #pragma unroll
                for (int q = 0; q < 8; q++)
                    st_dsmem4(sdst[q] + boff, v);
            }
            __syncwarp();
            if (jp == 0) {
                #pragma unroll
                for (int q = 0; q < 8; q++)
                    mbar_arrive_remote(((t + 1) & 1) ? amb1[q] : amb0[q]);
            }
        }
    }

    cluster_sync_full();   // all inbound traffic settled before any CTA exits
}

// =======================================================================
// Final projection
// =======================================================================
__global__ void proj_kernel(const float* __restrict__ ys,
                            const float* __restrict__ Wout,
                            const float* __restrict__ bout,
                            float* __restrict__ out)
{
    const int b    = blockIdx.x;
    const int c    = threadIdx.y;
    const int lane = threadIdx.x;
    const float* hrow = &ys[((size_t)b * TT + (TT - 1)) * HH];
    const float* wrow = &Wout[(size_t)c * HH];
    float s = 0.f;
    for (int k = lane; k < HH; k += 32) s += hrow[k] * wrow[k];
    #pragma unroll
    for (int o = 16; o > 0; o >>= 1) s += __shfl_down_sync(0xffffffffu, s, o);
    if (lane == 0) out[b * NCLS + c] = s + bout[c];
}

// =======================================================================
extern "C" void kernel_launch(void* const* d_in, const int* in_sizes, int n_in,
                              void* d_out, int out_size)
{
    (void)in_sizes; (void)n_in; (void)out_size;
    const float* x    = (const float*)d_in[0];
    const float* Wih[3] = {(const float*)d_in[1], (const float*)d_in[5], (const float*)d_in[9]};
    const float* Whh[3] = {(const float*)d_in[2], (const float*)d_in[6], (const float*)d_in[10]};
    const float* bih[3] = {(const float*)d_in[3], (const float*)d_in[7], (const float*)d_in[11]};
    const float* bhh[3] = {(const float*)d_in[4], (const float*)d_in[8], (const float*)d_in[12]};
    const float* Wout = (const float*)d_in[13];
    const float* bout = (const float*)d_in[14];
    float* out = (float*)d_out;

    float *xpPtr = nullptr, *ysPtr = nullptr;
    cudaGetSymbolAddress((void**)&xpPtr, g_xp);
    cudaGetSymbolAddress((void**)&ysPtr, g_ys);

    const dim3 ggrid(HH / 128, (BB * TT) / 128);
    for (int l = 0; l < 3; l++) {
        const float* A = (l == 0) ? x : ysPtr;
        const int K = (l == 0) ? II : HH;
        gemm_xproj<<<ggrid, 256>>>(A, Wih[l], bih[l], bhh[l], xpPtr, K);
        rnn_recur<<<128, 256>>>(xpPtr, Whh[l], ysPtr);
    }
    proj_kernel<<<64, dim3(32, 5)>>>(ysPtr, Wout, bout, out);
}

// round 6
// speedup vs baseline: 1.5848x; 1.5848x over previous
#include <cuda_runtime.h>
#include <cstdint>
#include <cstddef>

#define BB 64
#define TT 512
#define II 128
#define HH 512
#define NCLS 5

typedef unsigned long long u64;

// Scratch — static __device__ arrays per allocation rules.
__device__ float g_xp[(size_t)BB * TT * HH];
__device__ float g_ys[(size_t)BB * TT * HH];

// ---------------- packed f32x2 helpers ----------------
__device__ __forceinline__ u64 pk2(float x, float y) {
    u64 r; asm("mov.b64 %0, {%1,%2};" : "=l"(r) : "f"(x), "f"(y)); return r;
}
__device__ __forceinline__ float2 upk2(u64 v) {
    float2 f; asm("mov.b64 {%0,%1}, %2;" : "=f"(f.x), "=f"(f.y) : "l"(v)); return f;
}
__device__ __forceinline__ void fma2(u64 &d, u64 a, u64 b) {
    asm("fma.rn.f32x2 %0, %1, %2, %0;" : "+l"(d) : "l"(a), "l"(b));
}

// ---------------- cluster / mbarrier helpers ----------------
__device__ __forceinline__ uint32_t smem_u32(const void* p) {
    uint32_t a;
    asm("{ .reg .u64 t; cvta.to.shared.u64 t, %1; cvt.u32.u64 %0, t; }"
        : "=r"(a) : "l"(p));
    return a;
}
__device__ __forceinline__ uint32_t mapa_u32(uint32_t local, uint32_t rank) {
    uint32_t r;
    asm("mapa.shared::cluster.u32 %0, %1, %2;" : "=r"(r) : "r"(local), "r"(rank));
    return r;
}
__device__ __forceinline__ void mbar_init(uint32_t addr, uint32_t count) {
    asm volatile("mbarrier.init.shared.b64 [%0], %1;" :: "r"(addr), "r"(count) : "memory");
}
__device__ __forceinline__ void mbar_expect_tx(uint32_t addr, uint32_t bytes) {
    asm volatile("mbarrier.arrive.expect_tx.shared.b64 _, [%0], %1;"
                 :: "r"(addr), "r"(bytes) : "memory");
}
__device__ __forceinline__ void bulk_copy_cluster(uint32_t dst_cluster, uint32_t src_cta,
                                                  uint32_t bytes, uint32_t mbar_cluster) {
    asm volatile("cp.async.bulk.shared::cluster.shared::cta.mbarrier::complete_tx::bytes "
                 "[%0], [%1], %2, [%3];"
                 :: "r"(dst_cluster), "r"(src_cta), "r"(bytes), "r"(mbar_cluster) : "memory");
}
__device__ __forceinline__ void mbar_wait_cluster(uint32_t addr, uint32_t parity) {
    asm volatile(
        "{\n\t"
        ".reg .pred P;\n\t"
        "WLP%=:\n\t"
        "mbarrier.try_wait.parity.acquire.cluster.shared::cta.b64 P, [%0], %1, 0x989680;\n\t"
        "@P bra WDN%=;\n\t"
        "bra WLP%=;\n\t"
        "WDN%=:\n\t"
        "}"
        :: "r"(addr), "r"(parity) : "memory");
}
__device__ __forceinline__ void fence_proxy_async_cta() {
    asm volatile("fence.proxy.async.shared::cta;" ::: "memory");
}
__device__ __forceinline__ void cluster_sync_full() {
    asm volatile("barrier.cluster.arrive.aligned;" ::: "memory");
    asm volatile("barrier.cluster.wait.aligned;" ::: "memory");
}

// =======================================================================
// GEMM: C[M][HH] = A[M][K] @ W[HH][K]^T + b1 + b2  (software pipelined)
// =======================================================================
__global__ void __launch_bounds__(256, 1)
gemm_xproj(const float* __restrict__ A, const float* __restrict__ W,
           const float* __restrict__ b1, const float* __restrict__ b2,
           float* __restrict__ C, int K)
{
    __shared__ u64 As2[8][128];
    __shared__ u64 Bs2[8][128];

    const int tid = threadIdx.x;
    const int m0 = blockIdx.y * 128;
    const int n0 = blockIdx.x * 128;
    const int tx = tid & 15;
    const int ty = tid >> 4;

    const int r0  = tid >> 2;
    const int kq0 = tid & 3;

    u64 acc[8][8];
    #pragma unroll
    for (int i = 0; i < 8; i++)
        #pragma unroll
        for (int j = 0; j < 8; j++) acc[i][j] = 0ull;

    const float* pa0 = &A[(size_t)(m0 + r0)      * K + kq0 * 4];
    const float* pa1 = &A[(size_t)(m0 + 64 + r0) * K + kq0 * 4];
    const float* pw0 = &W[(size_t)(n0 + r0)      * K + kq0 * 4];
    const float* pw1 = &W[(size_t)(n0 + 64 + r0) * K + kq0 * 4];

    const int ktiles = K >> 4;
    float4 a0 = *(const float4*)pa0;
    float4 a1 = *(const float4*)pa1;
    float4 w0 = *(const float4*)pw0;
    float4 w1 = *(const float4*)pw1;

    for (int kt = 0; kt < ktiles; kt++) {
        __syncthreads();
        As2[kq0 * 2][r0]          = pk2(a0.x, a0.y);
        As2[kq0 * 2 + 1][r0]      = pk2(a0.z, a0.w);
        As2[kq0 * 2][64 + r0]     = pk2(a1.x, a1.y);
        As2[kq0 * 2 + 1][64 + r0] = pk2(a1.z, a1.w);
        Bs2[kq0 * 2][r0]          = pk2(w0.x, w0.y);
        Bs2[kq0 * 2 + 1][r0]      = pk2(w0.z, w0.w);
        Bs2[kq0 * 2][64 + r0]     = pk2(w1.x, w1.y);
        Bs2[kq0 * 2 + 1][64 + r0] = pk2(w1.z, w1.w);
        __syncthreads();

        if (kt + 1 < ktiles) {
            const int kb = (kt + 1) * 16;
            a0 = *(const float4*)(pa0 + kb);
            a1 = *(const float4*)(pa1 + kb);
            w0 = *(const float4*)(pw0 + kb);
            w1 = *(const float4*)(pw1 + kb);
        }

        #pragma unroll
        for (int k2 = 0; k2 < 8; k2++) {
            u64 af[8], bf[8];
            #pragma unroll
            for (int i = 0; i < 8; i++) af[i] = As2[k2][ty + 16 * i];
            #pragma unroll
            for (int j = 0; j < 8; j++) bf[j] = Bs2[k2][tx + 16 * j];
            #pragma unroll
            for (int i = 0; i < 8; i++)
                #pragma unroll
                for (int j = 0; j < 8; j++)
                    fma2(acc[i][j], af[i], bf[j]);
        }
    }

    float bias8[8];
    #pragma unroll
    for (int j = 0; j < 8; j++) {
        int n = n0 + tx + 16 * j;
        bias8[j] = b1[n] + b2[n];
    }
    #pragma unroll
    for (int i = 0; i < 8; i++) {
        const size_t m = (size_t)(m0 + ty + 16 * i);
        #pragma unroll
        for (int j = 0; j < 8; j++) {
            float2 p = upk2(acc[i][j]);
            C[m * HH + n0 + tx + 16 * j] = p.x + p.y + bias8[j];
        }
    }
}

// =======================================================================
// Recurrence: R4 bulk-engine exchange + 2-group batch pipelining.
// 16 clusters x 8 CTAs; CTA r owns cols [64r,64r+64) of 4 batch chains.
// Groups: g0 = batches {0,1}, g1 = batches {2,3}. Per step, each group:
//   per-warp wait on mbar[buf][g][kc] -> compute (2 batches, 512 fma-cyc)
//   -> stage partials -> sync -> reduce (tid<128) + relu + out_s + ys
//   -> sync -> tid<8 issue 8x512B bulk copies to peers' next buffer.
// Group g's engine/fabric latency hides under the other group's slot.
// =======================================================================
__global__ void __launch_bounds__(256, 1) __cluster_dims__(8, 1, 1)
rnn_recur(const float* __restrict__ xp, const float* __restrict__ Whh,
          float* __restrict__ ys)
{
    __shared__ ulonglong2 h_s[2][8][4][16];         // [buf][chunk][batch][64] 16KB
    __shared__ float redv[8][4][64];                // [chunk][batch][col] 8KB
    __shared__ __align__(16) float out_s[2][4][64]; // [buf][batch][col] 2KB
    __shared__ __align__(8) u64 mbar[2][2][8];      // [buf][group][chunk]

    const int tid   = threadIdx.x;
    const int r     = blockIdx.x & 7;               // cluster rank
    const int cl    = blockIdx.x >> 3;
    const int bg    = cl * 4;
    const int jbase = r * 64;

    const int jp = tid & 31;                        // lane
    const int kc = tid >> 5;                        // warp id == consumed chunk
    const int k0 = kc * 64;

    // ---- W_hh slice in registers, k-pair packed ----
    u64 w[2][32];
    #pragma unroll
    for (int jj = 0; jj < 2; jj++) {
        const float* wrow = &Whh[(size_t)(jbase + jp + jj * 32) * HH + k0];
        #pragma unroll
        for (int kp = 0; kp < 32; kp++) {
            float2 wv = *(const float2*)&wrow[2 * kp];
            w[jj][kp] = pk2(wv.x, wv.y);
        }
    }

    // ---- init: zero h buffers, init 32 mbarriers + first expects ----
    {
        float4* hs = (float4*)h_s;
        for (int i = tid; i < 2 * 8 * 4 * 16; i += 256)
            hs[i] = make_float4(0.f, 0.f, 0.f, 0.f);
    }
    const uint32_t mb_base = smem_u32(&mbar[0][0][0]);
    const uint32_t hbase   = smem_u32(&h_s[0][0][0][0]);
    const uint32_t obase   = smem_u32(&out_s[0][0][0]);
    if (tid < 32) {
        mbar_init(mb_base + (uint32_t)tid * 8u, 1);
        mbar_expect_tx(mb_base + (uint32_t)tid * 8u, 512u);
    }
    __syncthreads();
    cluster_sync_full();

    // my-warp wait mbarriers: [buf][group], chunk = kc
    uint32_t my_mb[2][2];
    #pragma unroll
    for (int b = 0; b < 2; b++)
        #pragma unroll
        for (int g = 0; g < 2; g++)
            my_mb[b][g] = mb_base + (uint32_t)(((b * 2 + g) * 8 + kc)) * 8u;

    // producer copy targets (tid < 8): peer q = tid, chunk = rank r
    uint32_t dst_q = 0;          // peer hbase + r*1024 (add buf*8192 + g*512)
    uint32_t rmb[2][2];          // remote mbar [buf][group] on peer q
    if (tid < 8) {
        const uint32_t q = (uint32_t)tid;
        dst_q = mapa_u32(hbase, q) + (uint32_t)r * 1024u;
        #pragma unroll
        for (int b = 0; b < 2; b++)
            #pragma unroll
            for (int g = 0; g < 2; g++)
                rmb[b][g] = mapa_u32(mb_base + (uint32_t)(((b * 2 + g) * 8 + r)) * 8u, q);
    }

    // reduce-role mapping (tid < 128): within group g, batch = 2g + rb
    const int rb = (tid >> 6) & 1;                  // 0..1
    const int cj = tid & 63;                        // col
    const bool red_act = (tid < 128);
    // xp/ys pointers for the two groups this thread reduces
    const float* xp_p0 = &xp[((size_t)(bg + rb)     * TT) * HH + jbase + cj];
    const float* xp_p1 = &xp[((size_t)(bg + 2 + rb) * TT) * HH + jbase + cj];
    float* ys_p0 = &ys[((size_t)(bg + rb)     * TT) * HH + jbase + cj];
    float* ys_p1 = &ys[((size_t)(bg + 2 + rb) * TT) * HH + jbase + cj];

    for (int t = 0; t < TT; t++) {
        const int os   = t & 1;
        const int wbuf = os ^ 1;
        const bool push = (t + 1 < TT);
        const uint32_t pwait = (uint32_t)(((t >> 1) + (os ^ 1)) & 1);

        float xpv0 = 0.f, xpv1 = 0.f;
        if (red_act) { xpv0 = __ldg(xp_p0); xpv1 = __ldg(xp_p1); }

        // =================== GROUP 0 (batches 0,1) ===================
        if (t > 0) {
            mbar_wait_cluster(my_mb[os][0], pwait);
            if (jp == 0) mbar_expect_tx(my_mb[os][0], 512u);
        }
        {
            const ulonglong2* hb = &h_s[os][kc][0][0];
            u64 a00 = 0ull, a10 = 0ull, a01 = 0ull, a11 = 0ull;
            #pragma unroll
            for (int kv = 0; kv < 16; kv++) {
                ulonglong2 h0 = hb[kv];        // batch 0
                ulonglong2 h1 = hb[16 + kv];   // batch 1
                fma2(a00, w[0][2 * kv],     h0.x);
                fma2(a00, w[0][2 * kv + 1], h0.y);
                fma2(a10, w[1][2 * kv],     h0.x);
                fma2(a10, w[1][2 * kv + 1], h0.y);
                fma2(a01, w[0][2 * kv],     h1.x);
                fma2(a01, w[0][2 * kv + 1], h1.y);
                fma2(a11, w[1][2 * kv],     h1.x);
                fma2(a11, w[1][2 * kv + 1], h1.y);
            }
            float2 p;
            p = upk2(a00); redv[kc][0][jp]      = p.x + p.y;
            p = upk2(a10); redv[kc][0][jp + 32] = p.x + p.y;
            p = upk2(a01); redv[kc][1][jp]      = p.x + p.y;
            p = upk2(a11); redv[kc][1][jp + 32] = p.x + p.y;
        }
        __syncthreads();
        if (red_act) {
            float s = xpv0;
            #pragma unroll
            for (int c = 0; c < 8; c++) s += redv[c][rb][cj];
            s = fmaxf(s, 0.f);
            out_s[os][rb][cj] = s;
            *ys_p0 = s; ys_p0 += HH;
        }
        __syncthreads();
        if (push && tid < 8) {
            fence_proxy_async_cta();
            bulk_copy_cluster(dst_q + (uint32_t)wbuf * 8192u,
                              obase + (uint32_t)os * 1024u,
                              512u, rmb[wbuf][0]);
        }

        // =================== GROUP 1 (batches 2,3) ===================
        if (t > 0) {
            mbar_wait_cluster(my_mb[os][1], pwait);
            if (jp == 0) mbar_expect_tx(my_mb[os][1], 512u);
        }
        {
            const ulonglong2* hb = &h_s[os][kc][2][0];
            u64 a00 = 0ull, a10 = 0ull, a01 = 0ull, a11 = 0ull;
            #pragma unroll
            for (int kv = 0; kv < 16; kv++) {
                ulonglong2 h0 = hb[kv];        // batch 2
                ulonglong2 h1 = hb[16 + kv];   // batch 3
                fma2(a00, w[0][2 * kv],     h0.x);
                fma2(a00, w[0][2 * kv + 1], h0.y);
                fma2(a10, w[1][2 * kv],     h0.x);
                fma2(a10, w[1][2 * kv + 1], h0.y);
                fma2(a01, w[0][2 * kv],     h1.x);
                fma2(a01, w[0][2 * kv + 1], h1.y);
                fma2(a11, w[1][2 * kv],     h1.x);
                fma2(a11, w[1][2 * kv + 1], h1.y);
            }
            float2 p;
            p = upk2(a00); redv[kc][2][jp]      = p.x + p.y;
            p = upk2(a10); redv[kc][2][jp + 32] = p.x + p.y;
            p = upk2(a01); redv[kc][3][jp]      = p.x + p.y;
            p = upk2(a11); redv[kc][3][jp + 32] = p.x + p.y;
        }
        __syncthreads();
        if (red_act) {
            float s = xpv1;
            #pragma unroll
            for (int c = 0; c < 8; c++) s += redv[c][2 + rb][cj];
            s = fmaxf(s, 0.f);
            out_s[os][2 + rb][cj] = s;
            *ys_p1 = s; ys_p1 += HH;
        }
        __syncthreads();
        if (push && tid < 8) {
            fence_proxy_async_cta();
            bulk_copy_cluster(dst_q + (uint32_t)wbuf * 8192u + 512u,
                              obase + (uint32_t)os * 1024u + 512u,
                              512u, rmb[wbuf][1]);
        }

        if (red_act) { xp_p0 += HH; xp_p1 += HH; }
    }

    cluster_sync_full();
}

// =======================================================================
// Final projection
// =======================================================================
__global__ void proj_kernel(const float* __restrict__ ys,
                            const float* __restrict__ Wout,
                            const float* __restrict__ bout,
                            float* __restrict__ out)
{
    const int b    = blockIdx.x;
    const int c    = threadIdx.y;
    const int lane = threadIdx.x;
    const float* hrow = &ys[((size_t)b * TT + (TT - 1)) * HH];
    const float* wrow = &Wout[(size_t)c * HH];
    float s = 0.f;
    for (int k = lane; k < HH; k += 32) s += hrow[k] * wrow[k];
    #pragma unroll
    for (int o = 16; o > 0; o >>= 1) s += __shfl_down_sync(0xffffffffu, s, o);
    if (lane == 0) out[b * NCLS + c] = s + bout[c];
}

// =======================================================================
extern "C" void kernel_launch(void* const* d_in, const int* in_sizes, int n_in,
                              void* d_out, int out_size)
{
    (void)in_sizes; (void)n_in; (void)out_size;
    const float* x    = (const float*)d_in[0];
    const float* Wih[3] = {(const float*)d_in[1], (const float*)d_in[5], (const float*)d_in[9]};
    const float* Whh[3] = {(const float*)d_in[2], (const float*)d_in[6], (const float*)d_in[10]};
    const float* bih[3] = {(const float*)d_in[3], (const float*)d_in[7], (const float*)d_in[11]};
    const float* bhh[3] = {(const float*)d_in[4], (const float*)d_in[8], (const float*)d_in[12]};
    const float* Wout = (const float*)d_in[13];
    const float* bout = (const float*)d_in[14];
    float* out = (float*)d_out;

    float *xpPtr = nullptr, *ysPtr = nullptr;
    cudaGetSymbolAddress((void**)&xpPtr, g_xp);
    cudaGetSymbolAddress((void**)&ysPtr, g_ys);

    const dim3 ggrid(HH / 128, (BB * TT) / 128);
    for (int l = 0; l < 3; l++) {
        const float* A = (l == 0) ? x : ysPtr;
        const int K = (l == 0) ? II : HH;
        gemm_xproj<<<ggrid, 256>>>(A, Wih[l], bih[l], bhh[l], xpPtr, K);
        rnn_recur<<<128, 256>>>(xpPtr, Whh[l], ysPtr);
    }
    proj_kernel<<<64, dim3(32, 5)>>>(ysPtr, Wout, bout, out);
}

// round 7
// speedup vs baseline: 2.1550x; 1.3598x over previous
#include <cuda_runtime.h>
#include <cstdint>
#include <cstddef>

#define BB 64
#define TT 512
#define II 128
#define HH 512
#define NCLS 5

typedef unsigned long long u64;

// Scratch — static __device__ arrays per allocation rules.
__device__ float g_xp[(size_t)BB * TT * HH];
__device__ float g_ys[(size_t)BB * TT * HH];

// ---------------- packed f32x2 helpers ----------------
__device__ __forceinline__ u64 pk2(float x, float y) {
    u64 r; asm("mov.b64 %0, {%1,%2};" : "=l"(r) : "f"(x), "f"(y)); return r;
}
__device__ __forceinline__ float2 upk2(u64 v) {
    float2 f; asm("mov.b64 {%0,%1}, %2;" : "=f"(f.x), "=f"(f.y) : "l"(v)); return f;
}
__device__ __forceinline__ void fma2(u64 &d, u64 a, u64 b) {
    asm("fma.rn.f32x2 %0, %1, %2, %0;" : "+l"(d) : "l"(a), "l"(b));
}

// ---------------- cluster / mbarrier helpers ----------------
__device__ __forceinline__ uint32_t smem_u32(const void* p) {
    uint32_t a;
    asm("{ .reg .u64 t; cvta.to.shared.u64 t, %1; cvt.u32.u64 %0, t; }"
        : "=r"(a) : "l"(p));
    return a;
}
__device__ __forceinline__ uint32_t mapa_u32(uint32_t local, uint32_t rank) {
    uint32_t r;
    asm("mapa.shared::cluster.u32 %0, %1, %2;" : "=r"(r) : "r"(local), "r"(rank));
    return r;
}
__device__ __forceinline__ void mbar_init(uint32_t addr, uint32_t count) {
    asm volatile("mbarrier.init.shared.b64 [%0], %1;" :: "r"(addr), "r"(count) : "memory");
}
__device__ __forceinline__ void mbar_expect_tx(uint32_t addr, uint32_t bytes) {
    asm volatile("mbarrier.arrive.expect_tx.shared.b64 _, [%0], %1;"
                 :: "r"(addr), "r"(bytes) : "memory");
}
__device__ __forceinline__ void bulk_copy_cluster(uint32_t dst_cluster, uint32_t src_cta,
                                                  uint32_t bytes, uint32_t mbar_cluster) {
    asm volatile("cp.async.bulk.shared::cluster.shared::cta.mbarrier::complete_tx::bytes "
                 "[%0], [%1], %2, [%3];"
                 :: "r"(dst_cluster), "r"(src_cta), "r"(bytes), "r"(mbar_cluster) : "memory");
}
__device__ __forceinline__ void mbar_wait_cluster(uint32_t addr, uint32_t parity) {
    asm volatile(
        "{\n\t"
        ".reg .pred P;\n\t"
        "WLP%=:\n\t"
        "mbarrier.try_wait.parity.acquire.cluster.shared::cta.b64 P, [%0], %1, 0x989680;\n\t"
        "@P bra WDN%=;\n\t"
        "bra WLP%=;\n\t"
        "WDN%=:\n\t"
        "}"
        :: "r"(addr), "r"(parity) : "memory");
}
__device__ __forceinline__ void fence_proxy_async_cta() {
    asm volatile("fence.proxy.async.shared::cta;" ::: "memory");
}
__device__ __forceinline__ void cluster_sync_full() {
    asm volatile("barrier.cluster.arrive.aligned;" ::: "memory");
    asm volatile("barrier.cluster.wait.aligned;" ::: "memory");
}

// =======================================================================
// GEMM: C[M][HH] = A[M][K] @ W[HH][K]^T + b1 + b2  (software pipelined)
// =======================================================================
__global__ void __launch_bounds__(256, 1)
gemm_xproj(const float* __restrict__ A, const float* __restrict__ W,
           const float* __restrict__ b1, const float* __restrict__ b2,
           float* __restrict__ C, int K)
{
    __shared__ u64 As2[8][128];
    __shared__ u64 Bs2[8][128];

    const int tid = threadIdx.x;
    const int m0 = blockIdx.y * 128;
    const int n0 = blockIdx.x * 128;
    const int tx = tid & 15;
    const int ty = tid >> 4;

    const int r0  = tid >> 2;
    const int kq0 = tid & 3;

    u64 acc[8][8];
    #pragma unroll
    for (int i = 0; i < 8; i++)
        #pragma unroll
        for (int j = 0; j < 8; j++) acc[i][j] = 0ull;

    const float* pa0 = &A[(size_t)(m0 + r0)      * K + kq0 * 4];
    const float* pa1 = &A[(size_t)(m0 + 64 + r0) * K + kq0 * 4];
    const float* pw0 = &W[(size_t)(n0 + r0)      * K + kq0 * 4];
    const float* pw1 = &W[(size_t)(n0 + 64 + r0) * K + kq0 * 4];

    const int ktiles = K >> 4;
    float4 a0 = *(const float4*)pa0;
    float4 a1 = *(const float4*)pa1;
    float4 w0 = *(const float4*)pw0;
    float4 w1 = *(const float4*)pw1;

    for (int kt = 0; kt < ktiles; kt++) {
        __syncthreads();
        As2[kq0 * 2][r0]          = pk2(a0.x, a0.y);
        As2[kq0 * 2 + 1][r0]      = pk2(a0.z, a0.w);
        As2[kq0 * 2][64 + r0]     = pk2(a1.x, a1.y);
        As2[kq0 * 2 + 1][64 + r0] = pk2(a1.z, a1.w);
        Bs2[kq0 * 2][r0]          = pk2(w0.x, w0.y);
        Bs2[kq0 * 2 + 1][r0]      = pk2(w0.z, w0.w);
        Bs2[kq0 * 2][64 + r0]     = pk2(w1.x, w1.y);
        Bs2[kq0 * 2 + 1][64 + r0] = pk2(w1.z, w1.w);
        __syncthreads();

        if (kt + 1 < ktiles) {
            const int kb = (kt + 1) * 16;
            a0 = *(const float4*)(pa0 + kb);
            a1 = *(const float4*)(pa1 + kb);
            w0 = *(const float4*)(pw0 + kb);
            w1 = *(const float4*)(pw1 + kb);
        }

        #pragma unroll
        for (int k2 = 0; k2 < 8; k2++) {
            u64 af[8], bf[8];
            #pragma unroll
            for (int i = 0; i < 8; i++) af[i] = As2[k2][ty + 16 * i];
            #pragma unroll
            for (int j = 0; j < 8; j++) bf[j] = Bs2[k2][tx + 16 * j];
            #pragma unroll
            for (int i = 0; i < 8; i++)
                #pragma unroll
                for (int j = 0; j < 8; j++)
                    fma2(acc[i][j], af[i], bf[j]);
        }
    }

    float bias8[8];
    #pragma unroll
    for (int j = 0; j < 8; j++) {
        int n = n0 + tx + 16 * j;
        bias8[j] = b1[n] + b2[n];
    }
    #pragma unroll
    for (int i = 0; i < 8; i++) {
        const size_t m = (size_t)(m0 + ty + 16 * i);
        #pragma unroll
        for (int j = 0; j < 8; j++) {
            float2 p = upk2(acc[i][j]);
            C[m * HH + n0 + tx + 16 * j] = p.x + p.y + bias8[j];
        }
    }
}

// =======================================================================
// Recurrence: R4 exchange + TWO independent 4-batch chains per cluster.
// 8 clusters x 8 CTAs; cluster owns batches [8*cl, 8*cl+8): group 0 = first
// 4, group 1 = last 4. Per t the CTA runs slot(g=0) then slot(g=1); each
// slot = per-warp chunk wait + 1024-cyc compute + reduce + 8x1KB bulk push.
// Group g's exchange latency hides under the other group's full slot.
// =======================================================================
__global__ void __launch_bounds__(256, 1) __cluster_dims__(8, 1, 1)
rnn_recur(const float* __restrict__ xp, const float* __restrict__ Whh,
          float* __restrict__ ys)
{
    __shared__ ulonglong2 h_s[2][2][8][4][16];       // [g][buf][chunk][batch][64f] 32KB
    __shared__ float redv[8][4][64];                 // [chunk][batch][col] 8KB
    __shared__ __align__(16) float out_s[2][2][4][64]; // [g][buf][batch][col] 4KB
    __shared__ __align__(8) u64 mbar[2][2][8];       // [g][buf][chunk]

    const int tid   = threadIdx.x;
    const int r     = blockIdx.x & 7;                // cluster rank
    const int cl    = blockIdx.x >> 3;
    const int bg    = cl * 8;
    const int jbase = r * 64;

    const int jp = tid & 31;                         // lane
    const int kc = tid >> 5;                         // warp id == consumed chunk
    const int k0 = kc * 64;

    // ---- W_hh slice in registers, k-pair packed ----
    u64 w[2][32];
    #pragma unroll
    for (int jj = 0; jj < 2; jj++) {
        const float* wrow = &Whh[(size_t)(jbase + jp + jj * 32) * HH + k0];
        #pragma unroll
        for (int kp = 0; kp < 32; kp++) {
            float2 wv = *(const float2*)&wrow[2 * kp];
            w[jj][kp] = pk2(wv.x, wv.y);
        }
    }

    // ---- init: zero h buffers, init 32 mbarriers + first expects ----
    {
        float4* hs = (float4*)h_s;
        for (int i = tid; i < 2 * 2 * 8 * 4 * 16; i += 256)
            hs[i] = make_float4(0.f, 0.f, 0.f, 0.f);
    }
    const uint32_t mb_base = smem_u32(&mbar[0][0][0]);
    const uint32_t hbase   = smem_u32(&h_s[0][0][0][0][0]);
    const uint32_t obase   = smem_u32(&out_s[0][0][0][0]);
    if (tid < 32) {
        mbar_init(mb_base + (uint32_t)tid * 8u, 1);
        mbar_expect_tx(mb_base + (uint32_t)tid * 8u, 1024u);
    }
    __syncthreads();
    cluster_sync_full();

    // my-warp wait mbarriers: [g][buf], chunk = kc
    uint32_t my_mb[2][2];
    #pragma unroll
    for (int g = 0; g < 2; g++)
        #pragma unroll
        for (int b = 0; b < 2; b++)
            my_mb[g][b] = mb_base + (uint32_t)(((g * 2 + b) * 8 + kc)) * 8u;
    int par[2][2] = {{0, 0}, {0, 0}};

    // producer copy targets (tid < 8): peer q = tid, chunk = rank r
    uint32_t dst_q = 0;            // peer hbase + r*1024 (+ g*16384 + buf*8192)
    uint32_t rmb[2][2];            // remote mbar [g][buf] on peer q
    if (tid < 8) {
        const uint32_t q = (uint32_t)tid;
        dst_q = mapa_u32(hbase, q) + (uint32_t)r * 1024u;
        #pragma unroll
        for (int g = 0; g < 2; g++)
            #pragma unroll
            for (int b = 0; b < 2; b++)
                rmb[g][b] = mapa_u32(mb_base + (uint32_t)(((g * 2 + b) * 8 + r)) * 8u, q);
    }

    // reduce-role mapping: all 256 threads, one (batch,col) scalar per group
    const int cb = tid >> 6;                         // batch-in-group 0..3
    const int cj = tid & 63;                         // col
    const float* xp_p[2];
    float*       ys_p[2];
    #pragma unroll
    for (int g = 0; g < 2; g++) {
        xp_p[g] = &xp[((size_t)(bg + g * 4 + cb) * TT) * HH + jbase + cj];
        ys_p[g] = &ys[((size_t)(bg + g * 4 + cb) * TT) * HH + jbase + cj];
    }

    for (int t = 0; t < TT; t++) {
        const int os   = t & 1;
        const int wbuf = os ^ 1;
        const bool push = (t + 1 < TT);

        float xpv[2];
        xpv[0] = __ldg(xp_p[0]);
        xpv[1] = __ldg(xp_p[1]);

        #pragma unroll
        for (int g = 0; g < 2; g++) {
            // ---- per-warp wait for MY chunk of group g (skip t=0: zeros) ----
            if (t > 0) {
                mbar_wait_cluster(my_mb[g][os], par[g][os]);
                if (jp == 0) mbar_expect_tx(my_mb[g][os], 1024u);
                par[g][os] ^= 1;
            }

            // ---- partial GEMV: W from regs, h broadcast from smem ----
            const ulonglong2* hb = &h_s[g][os][kc][0][0];
            u64 acc0[4], acc1[4];
            #pragma unroll
            for (int b = 0; b < 4; b++) {
                u64 a0 = 0ull, a1 = 0ull;
                #pragma unroll
                for (int kv = 0; kv < 16; kv++) {
                    ulonglong2 hv = hb[b * 16 + kv];
                    fma2(a0, w[0][2 * kv],     hv.x);
                    fma2(a0, w[0][2 * kv + 1], hv.y);
                    fma2(a1, w[1][2 * kv],     hv.x);
                    fma2(a1, w[1][2 * kv + 1], hv.y);
                }
                acc0[b] = a0; acc1[b] = a1;
            }

            // ---- stage partials ----
            #pragma unroll
            for (int b = 0; b < 4; b++) {
                float2 p0 = upk2(acc0[b]);
                float2 p1 = upk2(acc1[b]);
                redv[kc][b][jp]      = p0.x + p0.y;
                redv[kc][b][jp + 32] = p1.x + p1.y;
            }
            __syncthreads();

            // ---- reduce 8 chunks + xproj + relu ----
            {
                float s = xpv[g];
                #pragma unroll
                for (int c = 0; c < 8; c++) s += redv[c][cb][cj];
                s = fmaxf(s, 0.f);
                out_s[g][os][cb][cj] = s;
                *ys_p[g] = s;
                ys_p[g] += HH;
            }
            __syncthreads();

            // ---- async bulk push: 8 threads, 1KB to each peer ----
            if (push && tid < 8) {
                fence_proxy_async_cta();
                bulk_copy_cluster(dst_q + (uint32_t)g * 16384u + (uint32_t)wbuf * 8192u,
                                  obase + (uint32_t)g * 2048u + (uint32_t)os * 1024u,
                                  1024u, rmb[g][wbuf]);
            }
        }

        xp_p[0] += HH;
        xp_p[1] += HH;
    }

    cluster_sync_full();
}

// =======================================================================
// Final projection
// =======================================================================
__global__ void proj_kernel(const float* __restrict__ ys,
                            const float* __restrict__ Wout,
                            const float* __restrict__ bout,
                            float* __restrict__ out)
{
    const int b    = blockIdx.x;
    const int c    = threadIdx.y;
    const int lane = threadIdx.x;
    const float* hrow = &ys[((size_t)b * TT + (TT - 1)) * HH];
    const float* wrow = &Wout[(size_t)c * HH];
    float s = 0.f;
    for (int k = lane; k < HH; k += 32) s += hrow[k] * wrow[k];
    #pragma unroll
    for (int o = 16; o > 0; o >>= 1) s += __shfl_down_sync(0xffffffffu, s, o);
    if (lane == 0) out[b * NCLS + c] = s + bout[c];
}

// =======================================================================
extern "C" void kernel_launch(void* const* d_in, const int* in_sizes, int n_in,
                              void* d_out, int out_size)
{
    (void)in_sizes; (void)n_in; (void)out_size;
    const float* x    = (const float*)d_in[0];
    const float* Wih[3] = {(const float*)d_in[1], (const float*)d_in[5], (const float*)d_in[9]};
    const float* Whh[3] = {(const float*)d_in[2], (const float*)d_in[6], (const float*)d_in[10]};
    const float* bih[3] = {(const float*)d_in[3], (const float*)d_in[7], (const float*)d_in[11]};
    const float* bhh[3] = {(const float*)d_in[4], (const float*)d_in[8], (const float*)d_in[12]};
    const float* Wout = (const float*)d_in[13];
    const float* bout = (const float*)d_in[14];
    float* out = (float*)d_out;

    float *xpPtr = nullptr, *ysPtr = nullptr;
    cudaGetSymbolAddress((void**)&xpPtr, g_xp);
    cudaGetSymbolAddress((void**)&ysPtr, g_ys);

    const dim3 ggrid(HH / 128, (BB * TT) / 128);
    for (int l = 0; l < 3; l++) {
        const float* A = (l == 0) ? x : ysPtr;
        const int K = (l == 0) ? II : HH;
        gemm_xproj<<<ggrid, 256>>>(A, Wih[l], bih[l], bhh[l], xpPtr, K);
        rnn_recur<<<64, 256>>>(xpPtr, Whh[l], ysPtr);
    }
    proj_kernel<<<64, dim3(32, 5)>>>(ysPtr, Wout, bout, out);
}